// round 5
// baseline (speedup 1.0000x reference)
#include <cuda_runtime.h>

#define D_TOT 65536
#define S_TOT 1024
#define TS    128
#define NBLK  (D_TOT / 32)   // 2048 blocks
#define EPS   0.02f          // |bundled| below this -> precise-trig recompute

__device__ float        g_part[NBLK];
__device__ unsigned int g_ctr;   // zero at load; reset by the reducing block each call

// 32 d-rows per block, s in 128-wide float4 tiles. Double-buffered smem
// transpose with ONE barrier per tile: warps flow from hvs stores straight
// into the next tile's 8 hoisted LDG.128s, keeping DRAM reads in flight
// through the transpose/store phase. MUFU trig + precise fallback for
// near-zero bundled rows. Last block reduces dot(q,M) partials.
__global__ __launch_bounds__(256, 5) void reghd_main(
    const float* __restrict__ x,
    const float* __restrict__ weight,
    const float* __restrict__ bias,
    const float* __restrict__ alpha,
    const float* __restrict__ M,
    float* __restrict__ out)   // [0]=model_result, [1..D]=q, [1+D ...]=hvs (SIZE,D)
{
    __shared__ float4 sx[S_TOT / 4];
    __shared__ float4 sa[S_TOT / 4];
    __shared__ float  tile[2][32][TS + 1];   // double buffer, pad kills conflicts
    __shared__ float  bpart[32];
    __shared__ float  red[256];
    __shared__ bool   is_last;

    const int tx  = threadIdx.x;          // 0..31
    const int ty  = threadIdx.y;          // 0..7 (warp id)
    const int tid = ty * 32 + tx;
    const int d0  = blockIdx.x * 32;

    sx[tid] = ((const float4*)x)[tid];
    sa[tid] = ((const float4*)alpha)[tid];
    __syncthreads();

    float acc[4] = {0.f, 0.f, 0.f, 0.f};
    float* __restrict__ hvs = out + 1 + D_TOT;

    int p = 0;
    for (int s0 = 0; s0 < S_TOT; s0 += TS) {
        const float4 xv = sx[(s0 >> 2) + tx];
        const float4 av = sa[(s0 >> 2) + tx];

        // ---- hoist all 8 wide loads: MLP_p1 = 8 ----
        float4 w[4], b[4];
        #pragma unroll
        for (int r = 0; r < 4; r++) {
            const size_t base = (size_t)(d0 + ty + 8 * r) * S_TOT + (size_t)s0 + 4 * tx;
            w[r] = __ldcs((const float4*)(weight + base));
            b[r] = __ldcs((const float4*)(bias   + base));
        }

        #pragma unroll
        for (int r = 0; r < 4; r++) {
            const int dl = ty + 8 * r;
            const float p0 = xv.x * w[r].x, p1 = xv.y * w[r].y;
            const float p2 = xv.z * w[r].z, p3 = xv.w * w[r].w;
            const float e0 = __cosf(p0 + b[r].x) * __sinf(p0);
            const float e1 = __cosf(p1 + b[r].y) * __sinf(p1);
            const float e2 = __cosf(p2 + b[r].z) * __sinf(p2);
            const float e3 = __cosf(p3 + b[r].w) * __sinf(p3);

            tile[p][dl][4 * tx + 0] = e0;
            tile[p][dl][4 * tx + 1] = e1;
            tile[p][dl][4 * tx + 2] = e2;
            tile[p][dl][4 * tx + 3] = e3;

            acc[r] += fmaf(e0, av.x, fmaf(e1, av.y, fmaf(e2, av.z, e3 * av.w)));
        }

        __syncthreads();   // tile[p] complete; also guards buffer reuse (skew < 1 iter)

        #pragma unroll
        for (int k = 0; k < 16; k++) {
            const int sl = ty + 8 * k;
            __stcs(&hvs[(size_t)(s0 + sl) * D_TOT + (size_t)(d0 + tx)], tile[p][tx][sl]);
        }
        p ^= 1;            // next compute writes the other buffer — no second barrier
    }

    __syncthreads();

    // bundled -> (guarded) q -> per-block dot(q, M) partial
    const float* xs = (const float*)sx;
    const float* as = (const float*)sa;
    #pragma unroll
    for (int r = 0; r < 4; r++) {
        float v = acc[r];
        #pragma unroll
        for (int off = 16; off > 0; off >>= 1)
            v += __shfl_xor_sync(0xFFFFFFFFu, v, off);

        if (fabsf(v) < EPS) {
            // Borderline sign: precise-trig recompute (rare, ~0.16% of rows).
            const int d = d0 + ty + 8 * r;
            float s2 = 0.f;
            for (int s = tx; s < S_TOT; s += 32) {
                const float wv = weight[(size_t)d * S_TOT + s];
                const float bv = bias[(size_t)d * S_TOT + s];
                const float pp = xs[s] * wv;
                s2 += cosf(pp + bv) * sinf(pp) * as[s];
            }
            #pragma unroll
            for (int off = 16; off > 0; off >>= 1)
                s2 += __shfl_xor_sync(0xFFFFFFFFu, s2, off);
            v = s2;
        }
        if (tx == 0) {
            const int   d = d0 + ty + 8 * r;
            const float q = (v > 0.f) ? 1.f : -1.f;
            out[1 + d]        = q;
            bpart[ty + 8 * r] = q * M[d];
        }
    }
    __syncthreads();
    if (tid == 0) {
        float s = 0.f;
        #pragma unroll
        for (int i = 0; i < 32; i++) s += bpart[i];
        g_part[blockIdx.x] = s;
        __threadfence();
        const unsigned int prev = atomicAdd(&g_ctr, 1u);
        is_last = (prev == NBLK - 1);
    }
    __syncthreads();

    if (is_last) {
        float s = 0.f;
        for (int i = tid; i < NBLK; i += 256)
            s += g_part[i];
        red[tid] = s;
        __syncthreads();
        #pragma unroll
        for (int k = 128; k > 0; k >>= 1) {
            if (tid < k) red[tid] += red[tid + k];
            __syncthreads();
        }
        if (tid == 0) {
            out[0] = red[0];
            g_ctr  = 0;          // reset for next graph replay
        }
    }
}

extern "C" void kernel_launch(void* const* d_in, const int* in_sizes, int n_in,
                              void* d_out, int out_size) {
    const float* x      = (const float*)d_in[0];
    const float* weight = (const float*)d_in[1];
    const float* bias   = (const float*)d_in[2];
    const float* alpha  = (const float*)d_in[3];
    const float* M      = (const float*)d_in[4];
    float* out = (float*)d_out;

    dim3 blk(32, 8);
    reghd_main<<<NBLK, blk>>>(x, weight, bias, alpha, M, out);
}

// round 7
// speedup vs baseline: 1.0341x; 1.0341x over previous
#include <cuda_runtime.h>

#define D_TOT 65536
#define S_TOT 1024
#define TS    128
#define NBLK  (D_TOT / 32)   // 2048 blocks
#define EPS   0.02f          // |bundled| below this -> precise-trig recompute

__device__ float        g_part[NBLK];
__device__ unsigned int g_ctr;   // zero at load; reset by the reducing block each call

// Conflict-free transpose mapping: lane tx -> d-row dl = ty*4 + tx/8,
// s-offset 4*(tx%8). LDG.128 covers 4 d-rows x 128B (fully coalesced);
// scalar STS banks = (dl + s) mod 32 form a warp permutation -> zero
// bank conflicts on BOTH transpose sides. Fallback shuffles use the
// 8-lane group mask (v is group-uniform, NOT warp-uniform).
__global__ __launch_bounds__(256, 6) void reghd_main(
    const float* __restrict__ x,
    const float* __restrict__ weight,
    const float* __restrict__ bias,
    const float* __restrict__ alpha,
    const float* __restrict__ M,
    float* __restrict__ out)   // [0]=model_result, [1..D]=q, [1+D ...]=hvs (SIZE,D)
{
    __shared__ float4 sx[S_TOT / 4];
    __shared__ float4 sa[S_TOT / 4];
    __shared__ float  tile[32][TS + 1];   // pad 129: (dl + s) bank mapping
    __shared__ float  bpart[32];
    __shared__ float  red[256];
    __shared__ bool   is_last;

    const int tx  = threadIdx.x;              // 0..31
    const int ty  = threadIdx.y;              // 0..7 (warp id)
    const int tid = ty * 32 + tx;
    const int d0  = blockIdx.x * 32;
    const int dl  = ty * 4 + (tx >> 3);       // this thread's d-row (0..31)
    const int m   = tx & 7;                   // s-subgroup lane (0..7)
    const unsigned gmask = 0xFFu << (8 * (tx >> 3));  // 8-lane group mask

    sx[tid] = ((const float4*)x)[tid];
    sa[tid] = ((const float4*)alpha)[tid];
    __syncthreads();

    float acc = 0.f;                           // bundled partial for row dl
    float* __restrict__ hvs = out + 1 + D_TOT;

    for (int s0 = 0; s0 < S_TOT; s0 += TS) {
        #pragma unroll
        for (int r = 0; r < 4; r++) {
            const int    sloc = r * 32 + 4 * m;             // s within tile
            const size_t base = (size_t)(d0 + dl) * S_TOT + (size_t)(s0 + sloc);
            const float4 w  = __ldcs((const float4*)(weight + base));
            const float4 b  = __ldcs((const float4*)(bias   + base));
            const float4 xv = sx[((s0 + sloc) >> 2)];
            const float4 av = sa[((s0 + sloc) >> 2)];

            const float p0 = xv.x * w.x, p1 = xv.y * w.y;
            const float p2 = xv.z * w.z, p3 = xv.w * w.w;
            const float e0 = __cosf(p0 + b.x) * __sinf(p0);
            const float e1 = __cosf(p1 + b.y) * __sinf(p1);
            const float e2 = __cosf(p2 + b.z) * __sinf(p2);
            const float e3 = __cosf(p3 + b.w) * __sinf(p3);

            tile[dl][sloc + 0] = e0;          // conflict-free scalar STS
            tile[dl][sloc + 1] = e1;
            tile[dl][sloc + 2] = e2;
            tile[dl][sloc + 3] = e3;

            acc += fmaf(e0, av.x, fmaf(e1, av.y, fmaf(e2, av.z, e3 * av.w)));
        }
        __syncthreads();

        #pragma unroll
        for (int k = 0; k < 16; k++) {
            const int sl = ty + 8 * k;
            __stcs(&hvs[(size_t)(s0 + sl) * D_TOT + (size_t)(d0 + tx)], tile[tx][sl]);
        }
        __syncthreads();
    }

    // Reduce bundled within each 8-lane group (lanes sharing d-row dl).
    float v = acc;
    v += __shfl_xor_sync(0xFFFFFFFFu, v, 1);
    v += __shfl_xor_sync(0xFFFFFFFFu, v, 2);
    v += __shfl_xor_sync(0xFFFFFFFFu, v, 4);   // all 8 group lanes hold the row total

    if (fabsf(v) < EPS) {
        // Borderline sign: precise-trig recompute. v is uniform across the
        // 8-lane group, so all lanes of gmask enter together -> masked
        // collectives are legal here (full-mask would deadlock).
        const int d = d0 + dl;
        const float* xs = (const float*)sx;
        const float* as = (const float*)sa;
        float s2 = 0.f;
        for (int s = m; s < S_TOT; s += 8) {
            const float wv = weight[(size_t)d * S_TOT + s];
            const float bv = bias[(size_t)d * S_TOT + s];
            const float pp = xs[s] * wv;
            s2 += cosf(pp + bv) * sinf(pp) * as[s];
        }
        s2 += __shfl_xor_sync(gmask, s2, 1);
        s2 += __shfl_xor_sync(gmask, s2, 2);
        s2 += __shfl_xor_sync(gmask, s2, 4);
        v = s2;
    }
    if (m == 0) {
        const int   d = d0 + dl;
        const float q = (v > 0.f) ? 1.f : -1.f;
        out[1 + d] = q;
        bpart[dl]  = q * M[d];
    }
    __syncthreads();
    if (tid == 0) {
        float s = 0.f;
        #pragma unroll
        for (int i = 0; i < 32; i++) s += bpart[i];
        g_part[blockIdx.x] = s;
        __threadfence();
        const unsigned int prev = atomicAdd(&g_ctr, 1u);
        is_last = (prev == NBLK - 1);
    }
    __syncthreads();

    // Last-arriving block reduces all partials (fixed order -> deterministic).
    if (is_last) {
        float s = 0.f;
        for (int i = tid; i < NBLK; i += 256)
            s += g_part[i];
        red[tid] = s;
        __syncthreads();
        #pragma unroll
        for (int k = 128; k > 0; k >>= 1) {
            if (tid < k) red[tid] += red[tid + k];
            __syncthreads();
        }
        if (tid == 0) {
            out[0] = red[0];
            g_ctr  = 0;          // reset for next graph replay
        }
    }
}

extern "C" void kernel_launch(void* const* d_in, const int* in_sizes, int n_in,
                              void* d_out, int out_size) {
    const float* x      = (const float*)d_in[0];
    const float* weight = (const float*)d_in[1];
    const float* bias   = (const float*)d_in[2];
    const float* alpha  = (const float*)d_in[3];
    const float* M      = (const float*)d_in[4];
    float* out = (float*)d_out;

    dim3 blk(32, 8);
    reghd_main<<<NBLK, blk>>>(x, weight, bias, alpha, M, out);
}